// round 1
// baseline (speedup 1.0000x reference)
#include <cuda_runtime.h>
#include <math.h>

#define DMODEL 1024
#define NHEADS 16
#define DKH    64
#define BATCH  4
#define SEQ    2048
#define MR     (BATCH * SEQ)   // 8192 rows

// Scratch (allocation-free rule: __device__ globals)
static __device__ float g_Q[(size_t)MR * DMODEL];
static __device__ float g_K[(size_t)MR * DMODEL];
static __device__ float g_V[(size_t)MR * DMODEL];
static __device__ float g_A[(size_t)MR * DMODEL];

// ---------------------------------------------------------------------------
// C[M,N] = A[M,K] @ W[N,K]^T + bias[N]
// M = 8192, N = 1024, K = 1024.  Tile 128x128x16, 256 threads, 8x8 microtile.
// ---------------------------------------------------------------------------
__global__ __launch_bounds__(256) void gemm_nt_kernel(
    const float* __restrict__ A, const float* __restrict__ W,
    const float* __restrict__ bias, float* __restrict__ C)
{
    __shared__ float As[16][132];
    __shared__ float Bs[16][132];

    const int m0  = blockIdx.x * 128;
    const int n0  = blockIdx.y * 128;
    const int tid = threadIdx.x;
    const int tx  = tid & 15;
    const int ty  = tid >> 4;

    float acc[8][8];
#pragma unroll
    for (int i = 0; i < 8; i++)
#pragma unroll
        for (int j = 0; j < 8; j++) acc[i][j] = 0.0f;

    const float* Aptr = A + (size_t)m0 * DMODEL;
    const float* Wptr = W + (size_t)n0 * DMODEL;

    for (int k0 = 0; k0 < DMODEL; k0 += 16) {
#pragma unroll
        for (int it = 0; it < 2; it++) {
            int idx = tid + it * 256;        // 0..511
            int row = idx >> 2;              // 0..127
            int kc  = (idx & 3) * 4;         // 0,4,8,12
            float4 va = *(const float4*)(Aptr + (size_t)row * DMODEL + k0 + kc);
            As[kc + 0][row] = va.x;
            As[kc + 1][row] = va.y;
            As[kc + 2][row] = va.z;
            As[kc + 3][row] = va.w;
            float4 vb = *(const float4*)(Wptr + (size_t)row * DMODEL + k0 + kc);
            Bs[kc + 0][row] = vb.x;
            Bs[kc + 1][row] = vb.y;
            Bs[kc + 2][row] = vb.z;
            Bs[kc + 3][row] = vb.w;
        }
        __syncthreads();

#pragma unroll
        for (int k = 0; k < 16; k++) {
            float a[8], b[8];
            *(float4*)&a[0] = *(const float4*)&As[k][ty * 8];
            *(float4*)&a[4] = *(const float4*)&As[k][ty * 8 + 4];
            *(float4*)&b[0] = *(const float4*)&Bs[k][tx * 8];
            *(float4*)&b[4] = *(const float4*)&Bs[k][tx * 8 + 4];
#pragma unroll
            for (int i = 0; i < 8; i++)
#pragma unroll
                for (int j = 0; j < 8; j++)
                    acc[i][j] = fmaf(a[i], b[j], acc[i][j]);
        }
        __syncthreads();
    }

    float bvals[8];
#pragma unroll
    for (int j = 0; j < 8; j++) bvals[j] = bias[n0 + tx * 8 + j];

#pragma unroll
    for (int i = 0; i < 8; i++) {
        int row = m0 + ty * 8 + i;
        float* cp = C + (size_t)row * DMODEL + n0 + tx * 8;
        float4 r0, r1;
        r0.x = acc[i][0] + bvals[0];
        r0.y = acc[i][1] + bvals[1];
        r0.z = acc[i][2] + bvals[2];
        r0.w = acc[i][3] + bvals[3];
        r1.x = acc[i][4] + bvals[4];
        r1.y = acc[i][5] + bvals[5];
        r1.z = acc[i][6] + bvals[6];
        r1.w = acc[i][7] + bvals[7];
        *(float4*)(cp)     = r0;
        *(float4*)(cp + 4) = r1;
    }
}

// ---------------------------------------------------------------------------
// Fused flash-attention: per CTA, one (b,h) and a 128-row Q block.
// Tiles of 64 keys; online softmax; fp32 accumulation.
// smem: Qt[64][132] (dk-major), Kt[64][68] (dk-major),
//       Pt[64][132] (j-major over i), Vs[64][68] (row-major), mask[64]
// ---------------------------------------------------------------------------
#define QT_STRIDE 132
#define KT_STRIDE 68
#define ATTN_SMEM_FLOATS (64 * QT_STRIDE + 64 * KT_STRIDE + 64 * QT_STRIDE + 64 * KT_STRIDE)
#define ATTN_SMEM_BYTES  (ATTN_SMEM_FLOATS * 4 + 64 * 4)

__global__ __launch_bounds__(256) void attn_kernel(const int* __restrict__ mask)
{
    extern __shared__ float sm[];
    float* sq  = sm;                                   // Qt[dk][i]  64 x 132
    float* sk  = sq + 64 * QT_STRIDE;                  // Kt[dk][j]  64 x 68
    float* sp  = sk + 64 * KT_STRIDE;                  // Pt[j][i]   64 x 132
    float* sv  = sp + 64 * QT_STRIDE;                  // Vs[j][d]   64 x 68
    int*   smk = (int*)(sv + 64 * KT_STRIDE);          // mask[64]

    const int bh = blockIdx.y;       // 0..63
    const int b  = bh >> 4;
    const int h  = bh & 15;
    const int q0 = blockIdx.x * 128;
    const int tid = threadIdx.x;
    const int tx  = tid & 15;        // key-col group
    const int ty  = tid >> 4;        // q-row group

    const size_t rowbase = (size_t)(b * SEQ) * DMODEL + (size_t)h * DKH;
    const float* Qg = g_Q + rowbase + (size_t)q0 * DMODEL;
    const float* Kg = g_K + rowbase;
    const float* Vg = g_V + rowbase;
    const int*   mg = mask + b * SEQ;

    // Load Q block (128 x 64), transposed + pre-scaled by 1/sqrt(dk)
#pragma unroll
    for (int it = 0; it < 8; it++) {
        int idx = tid + it * 256;    // 0..2047
        int row = idx >> 4;          // 0..127
        int d0  = (idx & 15) * 4;
        float4 v = *(const float4*)(Qg + (size_t)row * DMODEL + d0);
        sq[(d0 + 0) * QT_STRIDE + row] = v.x * 0.125f;
        sq[(d0 + 1) * QT_STRIDE + row] = v.y * 0.125f;
        sq[(d0 + 2) * QT_STRIDE + row] = v.z * 0.125f;
        sq[(d0 + 3) * QT_STRIDE + row] = v.w * 0.125f;
    }

    float o[8][4];
    float mi[8], li[8];
#pragma unroll
    for (int r = 0; r < 8; r++) {
        mi[r] = -INFINITY;
        li[r] = 0.0f;
#pragma unroll
        for (int c = 0; c < 4; c++) o[r][c] = 0.0f;
    }

    for (int kb = 0; kb < SEQ / 64; kb++) {
        __syncthreads();   // previous PV phase done before overwriting K/V tiles

        // Load K tile (transposed) and V tile (row-major), plus mask slice
#pragma unroll
        for (int it = 0; it < 4; it++) {
            int idx = tid + it * 256;    // 0..1023
            int r   = idx >> 4;          // 0..63
            int d0  = (idx & 15) * 4;
            float4 kv = *(const float4*)(Kg + (size_t)(kb * 64 + r) * DMODEL + d0);
            sk[(d0 + 0) * KT_STRIDE + r] = kv.x;
            sk[(d0 + 1) * KT_STRIDE + r] = kv.y;
            sk[(d0 + 2) * KT_STRIDE + r] = kv.z;
            sk[(d0 + 3) * KT_STRIDE + r] = kv.w;
            float4 vv = *(const float4*)(Vg + (size_t)(kb * 64 + r) * DMODEL + d0);
            *(float4*)(sv + r * KT_STRIDE + d0) = vv;
        }
        if (tid < 64) smk[tid] = mg[kb * 64 + tid];
        __syncthreads();

        // S = (Q * scale) @ K^T for this tile: per thread 8 rows x 4 cols
        float s[8][4];
#pragma unroll
        for (int r = 0; r < 8; r++)
#pragma unroll
            for (int c = 0; c < 4; c++) s[r][c] = 0.0f;

#pragma unroll 4
        for (int dk = 0; dk < 64; dk++) {
            float a[8];
            *(float4*)&a[0] = *(const float4*)(sq + dk * QT_STRIDE + ty * 8);
            *(float4*)&a[4] = *(const float4*)(sq + dk * QT_STRIDE + ty * 8 + 4);
            float4 bv = *(const float4*)(sk + dk * KT_STRIDE + tx * 4);
#pragma unroll
            for (int r = 0; r < 8; r++) {
                s[r][0] = fmaf(a[r], bv.x, s[r][0]);
                s[r][1] = fmaf(a[r], bv.y, s[r][1]);
                s[r][2] = fmaf(a[r], bv.z, s[r][2]);
                s[r][3] = fmaf(a[r], bv.w, s[r][3]);
            }
        }

        // Mask
        int mk0 = smk[tx * 4 + 0];
        int mk1 = smk[tx * 4 + 1];
        int mk2 = smk[tx * 4 + 2];
        int mk3 = smk[tx * 4 + 3];
#pragma unroll
        for (int r = 0; r < 8; r++) {
            if (mk0 == 0) s[r][0] = -1e9f;
            if (mk1 == 0) s[r][1] = -1e9f;
            if (mk2 == 0) s[r][2] = -1e9f;
            if (mk3 == 0) s[r][3] = -1e9f;
        }

        // Online softmax update + write P (transposed)
#pragma unroll
        for (int r = 0; r < 8; r++) {
            float mx = fmaxf(fmaxf(s[r][0], s[r][1]), fmaxf(s[r][2], s[r][3]));
            mx = fmaxf(mx, __shfl_xor_sync(0xffffffffu, mx, 8));
            mx = fmaxf(mx, __shfl_xor_sync(0xffffffffu, mx, 4));
            mx = fmaxf(mx, __shfl_xor_sync(0xffffffffu, mx, 2));
            mx = fmaxf(mx, __shfl_xor_sync(0xffffffffu, mx, 1));
            float mnew  = fmaxf(mi[r], mx);
            float alpha = __expf(mi[r] - mnew);
            mi[r] = mnew;
            float rs = 0.0f;
#pragma unroll
            for (int c = 0; c < 4; c++) {
                s[r][c] = __expf(s[r][c] - mnew);
                rs += s[r][c];
            }
            rs += __shfl_xor_sync(0xffffffffu, rs, 8);
            rs += __shfl_xor_sync(0xffffffffu, rs, 4);
            rs += __shfl_xor_sync(0xffffffffu, rs, 2);
            rs += __shfl_xor_sync(0xffffffffu, rs, 1);
            li[r] = li[r] * alpha + rs;
#pragma unroll
            for (int c = 0; c < 4; c++) {
                o[r][c] *= alpha;
                sp[(tx * 4 + c) * QT_STRIDE + ty * 8 + r] = s[r][c];
            }
        }
        __syncthreads();

        // O += P @ V
#pragma unroll 4
        for (int j = 0; j < 64; j++) {
            float p[8];
            *(float4*)&p[0] = *(const float4*)(sp + j * QT_STRIDE + ty * 8);
            *(float4*)&p[4] = *(const float4*)(sp + j * QT_STRIDE + ty * 8 + 4);
            float4 vv = *(const float4*)(sv + j * KT_STRIDE + tx * 4);
#pragma unroll
            for (int r = 0; r < 8; r++) {
                o[r][0] = fmaf(p[r], vv.x, o[r][0]);
                o[r][1] = fmaf(p[r], vv.y, o[r][1]);
                o[r][2] = fmaf(p[r], vv.z, o[r][2]);
                o[r][3] = fmaf(p[r], vv.w, o[r][3]);
            }
        }
    }

    // Normalize and write to g_A  (row b*SEQ + q0 + ty*8 + r, col h*64 + tx*4)
#pragma unroll
    for (int r = 0; r < 8; r++) {
        float inv = 1.0f / li[r];
        float4 res;
        res.x = o[r][0] * inv;
        res.y = o[r][1] * inv;
        res.z = o[r][2] * inv;
        res.w = o[r][3] * inv;
        *(float4*)(g_A + rowbase + (size_t)(q0 + ty * 8 + r) * DMODEL + tx * 4) = res;
    }
}

// ---------------------------------------------------------------------------
extern "C" void kernel_launch(void* const* d_in, const int* in_sizes, int n_in,
                              void* d_out, int out_size)
{
    const float* x    = (const float*)d_in[0];
    const int*   mask = (const int*)  d_in[1];
    const float* Wq   = (const float*)d_in[2];
    const float* bq   = (const float*)d_in[3];
    const float* Wk   = (const float*)d_in[4];
    const float* bk   = (const float*)d_in[5];
    const float* Wv   = (const float*)d_in[6];
    const float* bv   = (const float*)d_in[7];
    const float* Wo   = (const float*)d_in[8];
    const float* bo   = (const float*)d_in[9];
    float* out = (float*)d_out;

    float *qp, *kp, *vp, *ap;
    cudaGetSymbolAddress((void**)&qp, g_Q);
    cudaGetSymbolAddress((void**)&kp, g_K);
    cudaGetSymbolAddress((void**)&vp, g_V);
    cudaGetSymbolAddress((void**)&ap, g_A);

    cudaFuncSetAttribute(attn_kernel,
                         cudaFuncAttributeMaxDynamicSharedMemorySize,
                         ATTN_SMEM_BYTES);

    dim3 gp(MR / 128, DMODEL / 128);   // 64 x 8
    gemm_nt_kernel<<<gp, 256>>>(x, Wq, bq, qp);
    gemm_nt_kernel<<<gp, 256>>>(x, Wk, bk, kp);
    gemm_nt_kernel<<<gp, 256>>>(x, Wv, bv, vp);

    dim3 ga(SEQ / 128, BATCH * NHEADS);  // 16 x 64
    attn_kernel<<<ga, 256, ATTN_SMEM_BYTES>>>(mask);

    gemm_nt_kernel<<<gp, 256>>>(ap, Wo, bo, out);
}

// round 3
// speedup vs baseline: 1.6165x; 1.6165x over previous
#include <cuda_runtime.h>
#include <cuda_bf16.h>
#include <math.h>
#include <stdint.h>

#define DMODEL 1024
#define NHEADS 16
#define DKH    64
#define BATCH  4
#define SEQ    2048
#define MR     (BATCH * SEQ)   // 8192 rows
#define DD     (DMODEL * DMODEL)

// Arch-specific feature gate: true only in an sm_10Xa device pass.
#if defined(__CUDA_ARCH_FEAT_SM103_ALL) || defined(__CUDA_ARCH_FEAT_SM100_ALL) || defined(__CUDA_ARCH_FEAT_SM101_ALL)
#define HAS_TCGEN05 1
#else
#define HAS_TCGEN05 0
#endif

// ---------------- scratch (allocation-free rule: __device__ globals) -------
static __device__ float g_Q[(size_t)MR * DMODEL];
static __device__ float g_K[(size_t)MR * DMODEL];
static __device__ float g_V[(size_t)MR * DMODEL];
static __device__ float g_A[(size_t)MR * DMODEL];

static __device__ __nv_bfloat16 g_xh[(size_t)MR * DMODEL];
static __device__ __nv_bfloat16 g_xl[(size_t)MR * DMODEL];
static __device__ __nv_bfloat16 g_wh[(size_t)4 * DD];
static __device__ __nv_bfloat16 g_wl[(size_t)4 * DD];
static __device__ __nv_bfloat16 g_ah[(size_t)MR * DMODEL];
static __device__ __nv_bfloat16 g_al[(size_t)MR * DMODEL];

// ---------------- PTX helpers (baseline, legal on compute_103) -------------
__device__ __forceinline__ uint32_t smem_u32(const void* p) {
    uint32_t a;
    asm("{ .reg .u64 t; cvta.to.shared.u64 t, %1; cvt.u32.u64 %0, t; }"
        : "=r"(a) : "l"(p));
    return a;
}

__device__ __forceinline__ void cp16(uint32_t dst, const void* src) {
    asm volatile("cp.async.cg.shared.global [%0], [%1], 16;\n"
                 :: "r"(dst), "l"(src) : "memory");
}
#define CP_COMMIT() asm volatile("cp.async.commit_group;\n" ::: "memory")
#define CP_WAIT(n)  asm volatile("cp.async.wait_group %0;\n" :: "n"(n) : "memory")

__device__ __forceinline__ void ldm4(uint32_t* r, uint32_t addr) {
    asm volatile("ldmatrix.sync.aligned.m8n8.x4.shared.b16 {%0,%1,%2,%3}, [%4];"
                 : "=r"(r[0]), "=r"(r[1]), "=r"(r[2]), "=r"(r[3]) : "r"(addr));
}

__device__ __forceinline__ void mma_bf16(float* c, const uint32_t* a,
                                         uint32_t b0, uint32_t b1) {
    asm volatile(
        "mma.sync.aligned.m16n8k16.row.col.f32.bf16.bf16.f32 "
        "{%0,%1,%2,%3}, {%4,%5,%6,%7}, {%8,%9}, {%0,%1,%2,%3};"
        : "+f"(c[0]), "+f"(c[1]), "+f"(c[2]), "+f"(c[3])
        : "r"(a[0]), "r"(a[1]), "r"(a[2]), "r"(a[3]), "r"(b0), "r"(b1));
}

// ---------------- sm_10Xa-only helpers -------------------------------------
#if HAS_TCGEN05
__device__ __forceinline__ uint32_t elect_one() {
    uint32_t pred;
    asm volatile(
        "{\n\t.reg .pred p;\n\telect.sync _|p, 0xFFFFFFFF;\n\t"
        "selp.b32 %0, 1, 0, p;\n\t}"
        : "=r"(pred));
    return pred;
}

__device__ __forceinline__ uint64_t mkdesc(uint32_t addr) {
    const uint64_t base = (2ull << 61) | (1ull << 46) | (64ull << 32) | (1ull << 16);
    return base | (uint64_t)((addr >> 4) & 0x3FFF);
}

__device__ __forceinline__ void mma_f16_ss(uint32_t d, uint64_t ad, uint64_t bd,
                                           uint32_t idesc, uint32_t en) {
    asm volatile(
        "{\n\t.reg .pred p;\n\tsetp.ne.u32 p, %5, 0;\n\t"
        "tcgen05.mma.cta_group::1.kind::f16 [%0], %1, %2, %3, {%4, %4, %4, %4}, p;\n\t}"
        :: "r"(d), "l"(ad), "l"(bd), "r"(idesc), "r"(0u), "r"(en) : "memory");
}

#define TC_ALLOC(sa, n)   asm volatile("tcgen05.alloc.cta_group::1.sync.aligned.shared::cta.b32 [%0], %1;" :: "r"(sa), "r"((uint32_t)(n)) : "memory")
#define TC_DEALLOC(t, n)  asm volatile("tcgen05.dealloc.cta_group::1.sync.aligned.b32 %0, %1;" :: "r"(t), "r"((uint32_t)(n)))
#define TC_RELINQ()       asm volatile("tcgen05.relinquish_alloc_permit.cta_group::1.sync.aligned;")
#define TC_COMMIT(mb)     asm volatile("tcgen05.commit.cta_group::1.mbarrier::arrive::one.shared::cluster.b64 [%0];" :: "r"(mb) : "memory")
#define TC_FENCE_AFTER()  asm volatile("tcgen05.fence::after_thread_sync;" ::: "memory")
#define TC_WAIT_LD()      asm volatile("tcgen05.wait::ld.sync.aligned;" ::: "memory")
#define MBAR_INIT(mb, n)  asm volatile("mbarrier.init.shared.b64 [%0], %1;" :: "r"(mb), "r"((uint32_t)(n)) : "memory")

#define MBAR_WAIT(mb, ph) do {                                                   \
    uint32_t _m = (mb), _p = (uint32_t)(ph), _d;                                 \
    asm volatile(                                                                \
        "{\n\t.reg .pred p;\n\t"                                                 \
        "mbarrier.try_wait.parity.acquire.cta.shared::cta.b64 p, [%1], %2;\n\t"  \
        "selp.b32 %0, 1, 0, p;\n\t}"                                             \
        : "=r"(_d) : "r"(_m), "r"(_p) : "memory");                               \
    if (!_d) {                                                                   \
        asm volatile(                                                            \
            "{\n\t.reg .pred P1;\n\t"                                            \
            "WL_%=:\n\t"                                                         \
            "mbarrier.try_wait.parity.acquire.cta.shared::cta.b64 P1, [%0], %1, 0x989680;\n\t" \
            "@P1 bra.uni WD_%=;\n\t"                                             \
            "bra.uni WL_%=;\n\t"                                                 \
            "WD_%=:\n\t}"                                                        \
            :: "r"(_m), "r"(_p) : "memory");                                     \
    }                                                                            \
} while (0)

#define TC_LD_X32(r, ta)                                                         \
    asm volatile(                                                                \
        "tcgen05.ld.sync.aligned.32x32b.x32.b32 "                                \
        "{%0, %1, %2, %3, %4, %5, %6, %7, "                                      \
        " %8, %9, %10, %11, %12, %13, %14, %15, "                                \
        " %16, %17, %18, %19, %20, %21, %22, %23, "                              \
        " %24, %25, %26, %27, %28, %29, %30, %31}, [%32];"                       \
        : "=r"((r)[0]),  "=r"((r)[1]),  "=r"((r)[2]),  "=r"((r)[3]),             \
          "=r"((r)[4]),  "=r"((r)[5]),  "=r"((r)[6]),  "=r"((r)[7]),             \
          "=r"((r)[8]),  "=r"((r)[9]),  "=r"((r)[10]), "=r"((r)[11]),            \
          "=r"((r)[12]), "=r"((r)[13]), "=r"((r)[14]), "=r"((r)[15]),            \
          "=r"((r)[16]), "=r"((r)[17]), "=r"((r)[18]), "=r"((r)[19]),            \
          "=r"((r)[20]), "=r"((r)[21]), "=r"((r)[22]), "=r"((r)[23]),            \
          "=r"((r)[24]), "=r"((r)[25]), "=r"((r)[26]), "=r"((r)[27]),            \
          "=r"((r)[28]), "=r"((r)[29]), "=r"((r)[30]), "=r"((r)[31])             \
        : "r"(ta))
#endif // HAS_TCGEN05

// ---------------- fp32 -> (bf16 hi, bf16 lo) conversion --------------------
__global__ __launch_bounds__(256) void cvt_hilo(
    const float* __restrict__ in,
    __nv_bfloat16* __restrict__ hi, __nv_bfloat16* __restrict__ lo, int n4)
{
    int i = blockIdx.x * 256 + threadIdx.x;
    if (i >= n4) return;
    float4 v = ((const float4*)in)[i];
    float f[4] = {v.x, v.y, v.z, v.w};
    __align__(8) __nv_bfloat16 h[4];
    __align__(8) __nv_bfloat16 l[4];
#pragma unroll
    for (int j = 0; j < 4; j++) {
        h[j] = __float2bfloat16(f[j]);
        l[j] = __float2bfloat16(f[j] - __bfloat162float(h[j]));
    }
    ((uint2*)hi)[i] = *(uint2*)h;
    ((uint2*)lo)[i] = *(uint2*)l;
}

// ---------------- bf16x3 GEMM: C[M,N]=A@W^T+bias, tile 128x128 -------------
#define TM 128
#define TN 128

// tcgen05 path constants
#define KB_T   64
#define NKB_T  (DMODEL / KB_T)         // 16
#define TSTG   (TM * KB_T * 2)         // 16384 B per bf16 submatrix
#define STAGE_T (4 * TSTG)             // 65536
// fallback (mma.sync) path constants
#define KB_F   32
#define NKB_F  (DMODEL / KB_F)         // 32
#define FSTG   (TM * KB_F * 2)         // 8192 B per bf16 submatrix
#define STAGE_F (4 * FSTG)             // 32768

#define GEMM_DSMEM (2 * STAGE_T + 1024)

#define GEMM_IDESC ((1u << 4) | (1u << 7) | (1u << 10) | ((TN / 8) << 17) | ((TM / 16) << 24))

// SW128 swizzle for 128B rows (tcgen05 tiles)
#define SWZ128(o) ((o) ^ (((o) >> 3) & 0x70))
// swizzle for 64B rows (fallback tiles): chunk ^= (row/2)&3
__device__ __forceinline__ uint32_t swz64(int row, int c16) {
    return (uint32_t)(row * 64 + ((c16 ^ ((row >> 1) & 3)) << 4));
}

#if HAS_TCGEN05
__device__ __forceinline__ void copy_tiles_t(
    const __nv_bfloat16* __restrict__ Ah, const __nv_bfloat16* __restrict__ Al,
    const __nv_bfloat16* __restrict__ Wh, const __nv_bfloat16* __restrict__ Wl,
    int m0, int n0, int kb, uint32_t base, int tid)
{
    const int koff = kb * KB_T;
#pragma unroll
    for (int i = 0; i < 4; i++) {            // 1024 chunks of 16B per matrix
        int c   = tid + i * 256;
        int row = c >> 3;
        int c8  = c & 7;
        uint32_t sw = base + SWZ128(row * 128 + c8 * 16);
        cp16(sw,            Ah + (size_t)(m0 + row) * DMODEL + koff + c8 * 8);
        cp16(sw + TSTG,     Al + (size_t)(m0 + row) * DMODEL + koff + c8 * 8);
        cp16(sw + 2 * TSTG, Wh + (size_t)(n0 + row) * DMODEL + koff + c8 * 8);
        cp16(sw + 3 * TSTG, Wl + (size_t)(n0 + row) * DMODEL + koff + c8 * 8);
    }
}
#endif

__device__ __forceinline__ void copy_tiles_f(
    const __nv_bfloat16* __restrict__ Ah, const __nv_bfloat16* __restrict__ Al,
    const __nv_bfloat16* __restrict__ Wh, const __nv_bfloat16* __restrict__ Wl,
    int m0, int n0, int kb, uint32_t base, int tid)
{
    const int koff = kb * KB_F;
#pragma unroll
    for (int i = 0; i < 2; i++) {            // 512 chunks of 16B per matrix
        int c   = tid + i * 256;
        int row = c >> 2;
        int c16 = c & 3;
        uint32_t sw = base + swz64(row, c16);
        cp16(sw,            Ah + (size_t)(m0 + row) * DMODEL + koff + c16 * 8);
        cp16(sw + FSTG,     Al + (size_t)(m0 + row) * DMODEL + koff + c16 * 8);
        cp16(sw + 2 * FSTG, Wh + (size_t)(n0 + row) * DMODEL + koff + c16 * 8);
        cp16(sw + 3 * FSTG, Wl + (size_t)(n0 + row) * DMODEL + koff + c16 * 8);
    }
}

__global__ __launch_bounds__(256, 1) void gemm_tc(
    const __nv_bfloat16* __restrict__ Ah, const __nv_bfloat16* __restrict__ Al,
    const __nv_bfloat16* __restrict__ Wh, const __nv_bfloat16* __restrict__ Wl,
    const float* __restrict__ bias, float* __restrict__ C)
{
    extern __shared__ char dsm[];
    const int tid = threadIdx.x;
    const int wid = tid >> 5;
    const int lid = tid & 31;
    const int m0  = blockIdx.x * TM;
    const int n0  = blockIdx.y * TN;

    uint32_t draw  = smem_u32(dsm);
    uint32_t abase = (draw + 1023) & ~1023u;

#if HAS_TCGEN05
    // ---------------- tcgen05 path ----------------
    __shared__ uint32_t s_tmem;
    __shared__ long long s_mbar[2];
    uint32_t mbar0 = smem_u32(&s_mbar[0]);
    uint32_t mbar1 = smem_u32(&s_mbar[1]);

    if (tid == 0) { MBAR_INIT(mbar0, 1); MBAR_INIT(mbar1, 1); }
    if (wid == 0) {
        TC_ALLOC(smem_u32(&s_tmem), TN);
        TC_RELINQ();
    }
    __syncthreads();
    const uint32_t tmem = s_tmem;

    int ph0 = 0, ph1 = 0;

    copy_tiles_t(Ah, Al, Wh, Wl, m0, n0, 0, abase, tid);
    CP_COMMIT();

    for (int kb = 0; kb < NKB_T; kb++) {
        const int s = kb & 1;
        if (kb + 1 < NKB_T) {
            if (kb >= 1) {
                if ((s ^ 1) == 0) { MBAR_WAIT(mbar0, ph0); ph0 ^= 1; }
                else              { MBAR_WAIT(mbar1, ph1); ph1 ^= 1; }
            }
            copy_tiles_t(Ah, Al, Wh, Wl, m0, n0, kb + 1,
                         abase + (uint32_t)(s ^ 1) * STAGE_T, tid);
            CP_COMMIT();
            CP_WAIT(1);
        } else {
            CP_WAIT(0);
        }
        asm volatile("fence.proxy.async.shared::cta;\n" ::: "memory");
        __syncthreads();

        if (wid == 0) {
            uint32_t soff = abase + (uint32_t)s * STAGE_T;
            uint64_t dah = mkdesc(soff);
            uint64_t dal = mkdesc(soff + TSTG);
            uint64_t dbh = mkdesc(soff + 2 * TSTG);
            uint64_t dbl = mkdesc(soff + 3 * TSTG);
            if (elect_one()) {
#pragma unroll
                for (int ks = 0; ks < 4; ks++) {
                    uint32_t en0 = (kb == 0 && ks == 0) ? 0u : 1u;
                    mma_f16_ss(tmem, dah + ks * 2, dbh + ks * 2, GEMM_IDESC, en0);
                    mma_f16_ss(tmem, dah + ks * 2, dbl + ks * 2, GEMM_IDESC, 1u);
                    mma_f16_ss(tmem, dal + ks * 2, dbh + ks * 2, GEMM_IDESC, 1u);
                }
                TC_COMMIT(s == 0 ? mbar0 : mbar1);
            }
        }
    }

    MBAR_WAIT(mbar0, ph0);
    MBAR_WAIT(mbar1, ph1);
    TC_FENCE_AFTER();

    if (wid < 4) {
        const int row = m0 + wid * 32 + lid;
        float* cp = C + (size_t)row * DMODEL + n0;
#pragma unroll 1
        for (int nb = 0; nb < TN / 32; nb++) {
            uint32_t r[32];
            TC_LD_X32(r, tmem + nb * 32);
            TC_WAIT_LD();
#pragma unroll
            for (int c = 0; c < 32; c += 4) {
                float4 o;
                o.x = __uint_as_float(r[c + 0]) + bias[n0 + nb * 32 + c + 0];
                o.y = __uint_as_float(r[c + 1]) + bias[n0 + nb * 32 + c + 1];
                o.z = __uint_as_float(r[c + 2]) + bias[n0 + nb * 32 + c + 2];
                o.w = __uint_as_float(r[c + 3]) + bias[n0 + nb * 32 + c + 3];
                *(float4*)(cp + nb * 32 + c) = o;
            }
        }
    }
    __syncthreads();
    if (wid == 0) TC_DEALLOC(tmem, TN);

#else
    // ---------------- mma.sync bf16x3 fallback ----------------
    const int wm = wid >> 1;   // 0..3 (m warp row, 32 rows each)
    const int wn = wid & 1;    // 0..1 (n warp col, 64 cols each)

    float acc[2][8][4];
#pragma unroll
    for (int mt = 0; mt < 2; mt++)
#pragma unroll
        for (int nt = 0; nt < 8; nt++)
#pragma unroll
            for (int j = 0; j < 4; j++) acc[mt][nt][j] = 0.0f;

    const int lrow = (lid & 7) + ((lid >> 3) & 1) * 8;  // row within 16-row tile
    const int lhalf = lid >> 4;                         // k-chunk half (0/1)

    copy_tiles_f(Ah, Al, Wh, Wl, m0, n0, 0, abase, tid);
    CP_COMMIT();

    for (int kb = 0; kb < NKB_F; kb++) {
        const uint32_t sbase = abase + (uint32_t)(kb & 1) * STAGE_F;
        if (kb + 1 < NKB_F) {
            copy_tiles_f(Ah, Al, Wh, Wl, m0, n0, kb + 1,
                         abase + (uint32_t)((kb + 1) & 1) * STAGE_F, tid);
            CP_COMMIT();
            CP_WAIT(1);
        } else {
            CP_WAIT(0);
        }
        __syncthreads();

#pragma unroll
        for (int ks = 0; ks < 2; ks++) {
            const int chunk = ks * 2 + lhalf;
            uint32_t bh[4][4], bl[4][4];
#pragma unroll
            for (int nt = 0; nt < 4; nt++) {
                int brow = wn * 64 + nt * 16 + lrow;
                uint32_t boff = swz64(brow, chunk);
                ldm4(bh[nt], sbase + 2 * FSTG + boff);
                ldm4(bl[nt], sbase + 3 * FSTG + boff);
            }
#pragma unroll
            for (int mt = 0; mt < 2; mt++) {
                int arow = wm * 32 + mt * 16 + lrow;
                uint32_t aoff = swz64(arow, chunk);
                uint32_t ah[4], al[4];
                ldm4(ah, sbase + aoff);
                ldm4(al, sbase + FSTG + aoff);
#pragma unroll
                for (int nt = 0; nt < 4; nt++) {
                    mma_bf16(acc[mt][2 * nt + 0], ah, bh[nt][0], bh[nt][2]);
                    mma_bf16(acc[mt][2 * nt + 1], ah, bh[nt][1], bh[nt][3]);
                    mma_bf16(acc[mt][2 * nt + 0], ah, bl[nt][0], bl[nt][2]);
                    mma_bf16(acc[mt][2 * nt + 1], ah, bl[nt][1], bl[nt][3]);
                    mma_bf16(acc[mt][2 * nt + 0], al, bh[nt][0], bh[nt][2]);
                    mma_bf16(acc[mt][2 * nt + 1], al, bh[nt][1], bh[nt][3]);
                }
            }
        }
        __syncthreads();
    }

    // epilogue: bias + store (frag layout: lane = 8*(c&1)? standard m16n8)
#pragma unroll
    for (int mt = 0; mt < 2; mt++) {
        int r0 = m0 + wm * 32 + mt * 16 + (lid >> 2);
#pragma unroll
        for (int nt = 0; nt < 8; nt++) {
            int c0 = n0 + wn * 64 + nt * 8 + (lid & 3) * 2;
            float b0 = bias[c0], b1 = bias[c0 + 1];
            float2 u, v;
            u.x = acc[mt][nt][0] + b0;
            u.y = acc[mt][nt][1] + b1;
            v.x = acc[mt][nt][2] + b0;
            v.y = acc[mt][nt][3] + b1;
            *(float2*)(C + (size_t)r0 * DMODEL + c0)       = u;
            *(float2*)(C + (size_t)(r0 + 8) * DMODEL + c0) = v;
        }
    }
#endif
}

// ---------------------------------------------------------------------------
// Fused flash-attention (unchanged from R1): fp32, online softmax.
// ---------------------------------------------------------------------------
#define QT_STRIDE 132
#define KT_STRIDE 68
#define ATTN_SMEM_FLOATS (64 * QT_STRIDE + 64 * KT_STRIDE + 64 * QT_STRIDE + 64 * KT_STRIDE)
#define ATTN_SMEM_BYTES  (ATTN_SMEM_FLOATS * 4 + 64 * 4)

__global__ __launch_bounds__(256) void attn_kernel(const int* __restrict__ mask)
{
    extern __shared__ float sm[];
    float* sq  = sm;
    float* sk  = sq + 64 * QT_STRIDE;
    float* sp  = sk + 64 * KT_STRIDE;
    float* sv  = sp + 64 * QT_STRIDE;
    int*   smk = (int*)(sv + 64 * KT_STRIDE);

    const int bh = blockIdx.y;
    const int b  = bh >> 4;
    const int h  = bh & 15;
    const int q0 = blockIdx.x * 128;
    const int tid = threadIdx.x;
    const int tx  = tid & 15;
    const int ty  = tid >> 4;

    const size_t rowbase = (size_t)(b * SEQ) * DMODEL + (size_t)h * DKH;
    const float* Qg = g_Q + rowbase + (size_t)q0 * DMODEL;
    const float* Kg = g_K + rowbase;
    const float* Vg = g_V + rowbase;
    const int*   mg = mask + b * SEQ;

#pragma unroll
    for (int it = 0; it < 8; it++) {
        int idx = tid + it * 256;
        int row = idx >> 4;
        int d0  = (idx & 15) * 4;
        float4 v = *(const float4*)(Qg + (size_t)row * DMODEL + d0);
        sq[(d0 + 0) * QT_STRIDE + row] = v.x * 0.125f;
        sq[(d0 + 1) * QT_STRIDE + row] = v.y * 0.125f;
        sq[(d0 + 2) * QT_STRIDE + row] = v.z * 0.125f;
        sq[(d0 + 3) * QT_STRIDE + row] = v.w * 0.125f;
    }

    float o[8][4];
    float mi[8], li[8];
#pragma unroll
    for (int r = 0; r < 8; r++) {
        mi[r] = -INFINITY;
        li[r] = 0.0f;
#pragma unroll
        for (int c = 0; c < 4; c++) o[r][c] = 0.0f;
    }

    for (int kb = 0; kb < SEQ / 64; kb++) {
        __syncthreads();

#pragma unroll
        for (int it = 0; it < 4; it++) {
            int idx = tid + it * 256;
            int r   = idx >> 4;
            int d0  = (idx & 15) * 4;
            float4 kv = *(const float4*)(Kg + (size_t)(kb * 64 + r) * DMODEL + d0);
            sk[(d0 + 0) * KT_STRIDE + r] = kv.x;
            sk[(d0 + 1) * KT_STRIDE + r] = kv.y;
            sk[(d0 + 2) * KT_STRIDE + r] = kv.z;
            sk[(d0 + 3) * KT_STRIDE + r] = kv.w;
            float4 vv = *(const float4*)(Vg + (size_t)(kb * 64 + r) * DMODEL + d0);
            *(float4*)(sv + r * KT_STRIDE + d0) = vv;
        }
        if (tid < 64) smk[tid] = mg[kb * 64 + tid];
        __syncthreads();

        float s[8][4];
#pragma unroll
        for (int r = 0; r < 8; r++)
#pragma unroll
            for (int c = 0; c < 4; c++) s[r][c] = 0.0f;

#pragma unroll 4
        for (int dk = 0; dk < 64; dk++) {
            float a[8];
            *(float4*)&a[0] = *(const float4*)(sq + dk * QT_STRIDE + ty * 8);
            *(float4*)&a[4] = *(const float4*)(sq + dk * QT_STRIDE + ty * 8 + 4);
            float4 bv = *(const float4*)(sk + dk * KT_STRIDE + tx * 4);
#pragma unroll
            for (int r = 0; r < 8; r++) {
                s[r][0] = fmaf(a[r], bv.x, s[r][0]);
                s[r][1] = fmaf(a[r], bv.y, s[r][1]);
                s[r][2] = fmaf(a[r], bv.z, s[r][2]);
                s[r][3] = fmaf(a[r], bv.w, s[r][3]);
            }
        }

        int mk0 = smk[tx * 4 + 0];
        int mk1 = smk[tx * 4 + 1];
        int mk2 = smk[tx * 4 + 2];
        int mk3 = smk[tx * 4 + 3];
#pragma unroll
        for (int r = 0; r < 8; r++) {
            if (mk0 == 0) s[r][0] = -1e9f;
            if (mk1 == 0) s[r][1] = -1e9f;
            if (mk2 == 0) s[r][2] = -1e9f;
            if (mk3 == 0) s[r][3] = -1e9f;
        }

#pragma unroll
        for (int r = 0; r < 8; r++) {
            float mx = fmaxf(fmaxf(s[r][0], s[r][1]), fmaxf(s[r][2], s[r][3]));
            mx = fmaxf(mx, __shfl_xor_sync(0xffffffffu, mx, 8));
            mx = fmaxf(mx, __shfl_xor_sync(0xffffffffu, mx, 4));
            mx = fmaxf(mx, __shfl_xor_sync(0xffffffffu, mx, 2));
            mx = fmaxf(mx, __shfl_xor_sync(0xffffffffu, mx, 1));
            float mnew  = fmaxf(mi[r], mx);
            float alpha = __expf(mi[r] - mnew);
            mi[r] = mnew;
            float rs = 0.0f;
#pragma unroll
            for (int c = 0; c < 4; c++) {
                s[r][c] = __expf(s[r][c] - mnew);
                rs += s[r][c];
            }
            rs += __shfl_xor_sync(0xffffffffu, rs, 8);
            rs += __shfl_xor_sync(0xffffffffu, rs, 4);
            rs += __shfl_xor_sync(0xffffffffu, rs, 2);
            rs += __shfl_xor_sync(0xffffffffu, rs, 1);
            li[r] = li[r] * alpha + rs;
#pragma unroll
            for (int c = 0; c < 4; c++) {
                o[r][c] *= alpha;
                sp[(tx * 4 + c) * QT_STRIDE + ty * 8 + r] = s[r][c];
            }
        }
        __syncthreads();

#pragma unroll 4
        for (int j = 0; j < 64; j++) {
            float p[8];
            *(float4*)&p[0] = *(const float4*)(sp + j * QT_STRIDE + ty * 8);
            *(float4*)&p[4] = *(const float4*)(sp + j * QT_STRIDE + ty * 8 + 4);
            float4 vv = *(const float4*)(sv + j * KT_STRIDE + tx * 4);
#pragma unroll
            for (int r = 0; r < 8; r++) {
                o[r][0] = fmaf(p[r], vv.x, o[r][0]);
                o[r][1] = fmaf(p[r], vv.y, o[r][1]);
                o[r][2] = fmaf(p[r], vv.z, o[r][2]);
                o[r][3] = fmaf(p[r], vv.w, o[r][3]);
            }
        }
    }

#pragma unroll
    for (int r = 0; r < 8; r++) {
        float inv = 1.0f / li[r];
        float4 res;
        res.x = o[r][0] * inv;
        res.y = o[r][1] * inv;
        res.z = o[r][2] * inv;
        res.w = o[r][3] * inv;
        *(float4*)(g_A + rowbase + (size_t)(q0 + ty * 8 + r) * DMODEL + tx * 4) = res;
    }
}

// ---------------------------------------------------------------------------
extern "C" void kernel_launch(void* const* d_in, const int* in_sizes, int n_in,
                              void* d_out, int out_size)
{
    const float* x    = (const float*)d_in[0];
    const int*   mask = (const int*)  d_in[1];
    const float* Wq   = (const float*)d_in[2];
    const float* bq   = (const float*)d_in[3];
    const float* Wk   = (const float*)d_in[4];
    const float* bk   = (const float*)d_in[5];
    const float* Wv   = (const float*)d_in[6];
    const float* bv   = (const float*)d_in[7];
    const float* Wo   = (const float*)d_in[8];
    const float* bo   = (const float*)d_in[9];
    float* out = (float*)d_out;

    float *qp, *kp, *vp, *ap;
    __nv_bfloat16 *xh, *xl, *wh, *wl, *ah, *al;
    cudaGetSymbolAddress((void**)&qp, g_Q);
    cudaGetSymbolAddress((void**)&kp, g_K);
    cudaGetSymbolAddress((void**)&vp, g_V);
    cudaGetSymbolAddress((void**)&ap, g_A);
    cudaGetSymbolAddress((void**)&xh, g_xh);
    cudaGetSymbolAddress((void**)&xl, g_xl);
    cudaGetSymbolAddress((void**)&wh, g_wh);
    cudaGetSymbolAddress((void**)&wl, g_wl);
    cudaGetSymbolAddress((void**)&ah, g_ah);
    cudaGetSymbolAddress((void**)&al, g_al);

    cudaFuncSetAttribute(attn_kernel,
                         cudaFuncAttributeMaxDynamicSharedMemorySize,
                         ATTN_SMEM_BYTES);
    cudaFuncSetAttribute(gemm_tc,
                         cudaFuncAttributeMaxDynamicSharedMemorySize,
                         GEMM_DSMEM);

    const int n4x = MR * DMODEL / 4;
    const int n4w = DD / 4;

    cvt_hilo<<<n4x / 256, 256>>>(x, xh, xl, n4x);
    cvt_hilo<<<n4w / 256, 256>>>(Wq, wh + 0 * (size_t)DD, wl + 0 * (size_t)DD, n4w);
    cvt_hilo<<<n4w / 256, 256>>>(Wk, wh + 1 * (size_t)DD, wl + 1 * (size_t)DD, n4w);
    cvt_hilo<<<n4w / 256, 256>>>(Wv, wh + 2 * (size_t)DD, wl + 2 * (size_t)DD, n4w);
    cvt_hilo<<<n4w / 256, 256>>>(Wo, wh + 3 * (size_t)DD, wl + 3 * (size_t)DD, n4w);

    dim3 gg(MR / TM, DMODEL / TN);   // 64 x 8
    gemm_tc<<<gg, 256, GEMM_DSMEM>>>(xh, xl, wh + 0 * (size_t)DD, wl + 0 * (size_t)DD, bq, qp);
    gemm_tc<<<gg, 256, GEMM_DSMEM>>>(xh, xl, wh + 1 * (size_t)DD, wl + 1 * (size_t)DD, bk, kp);
    gemm_tc<<<gg, 256, GEMM_DSMEM>>>(xh, xl, wh + 2 * (size_t)DD, wl + 2 * (size_t)DD, bv, vp);

    dim3 ga(SEQ / 128, BATCH * NHEADS);
    attn_kernel<<<ga, 256, ATTN_SMEM_BYTES>>>(mask);

    cvt_hilo<<<n4x / 256, 256>>>(ap, ah, al, n4x);
    gemm_tc<<<gg, 256, GEMM_DSMEM>>>(ah, al, wh + 3 * (size_t)DD, wl + 3 * (size_t)DD, bo, out);
}

// round 6
// speedup vs baseline: 3.6068x; 2.2312x over previous
#include <cuda_runtime.h>
#include <cuda_bf16.h>
#include <math.h>
#include <stdint.h>

#define DMODEL 1024
#define NHEADS 16
#define DKH    64
#define BATCH  4
#define SEQ    2048
#define MR     (BATCH * SEQ)   // 8192 rows
#define DD     (DMODEL * DMODEL)

// Arch-specific feature gate: true only in an sm_10Xa device pass.
#if defined(__CUDA_ARCH_FEAT_SM103_ALL) || defined(__CUDA_ARCH_FEAT_SM100_ALL) || defined(__CUDA_ARCH_FEAT_SM101_ALL)
#define HAS_TCGEN05 1
#else
#define HAS_TCGEN05 0
#endif

// ---------------- scratch (allocation-free rule: __device__ globals) -------
static __device__ __nv_bfloat16 g_xh[(size_t)MR * DMODEL];
static __device__ __nv_bfloat16 g_xl[(size_t)MR * DMODEL];
static __device__ __nv_bfloat16 g_wh[(size_t)4 * DD];
static __device__ __nv_bfloat16 g_wl[(size_t)4 * DD];
static __device__ __nv_bfloat16 g_qh[(size_t)MR * DMODEL];
static __device__ __nv_bfloat16 g_ql[(size_t)MR * DMODEL];
static __device__ __nv_bfloat16 g_kh[(size_t)MR * DMODEL];
static __device__ __nv_bfloat16 g_kl[(size_t)MR * DMODEL];
static __device__ __nv_bfloat16 g_vh[(size_t)MR * DMODEL];
static __device__ __nv_bfloat16 g_vl[(size_t)MR * DMODEL];
static __device__ __nv_bfloat16 g_ah[(size_t)MR * DMODEL];
static __device__ __nv_bfloat16 g_al[(size_t)MR * DMODEL];

// ---------------- PTX helpers (baseline, legal on compute_103) -------------
__device__ __forceinline__ uint32_t smem_u32(const void* p) {
    uint32_t a;
    asm("{ .reg .u64 t; cvta.to.shared.u64 t, %1; cvt.u32.u64 %0, t; }"
        : "=r"(a) : "l"(p));
    return a;
}

__device__ __forceinline__ void cp16(uint32_t dst, const void* src) {
    asm volatile("cp.async.cg.shared.global [%0], [%1], 16;\n"
                 :: "r"(dst), "l"(src) : "memory");
}
#define CP_COMMIT() asm volatile("cp.async.commit_group;\n" ::: "memory")
#define CP_WAIT(n)  asm volatile("cp.async.wait_group %0;\n" :: "n"(n) : "memory")

__device__ __forceinline__ void ldm4(uint32_t* r, uint32_t addr) {
    asm volatile("ldmatrix.sync.aligned.m8n8.x4.shared.b16 {%0,%1,%2,%3}, [%4];"
                 : "=r"(r[0]), "=r"(r[1]), "=r"(r[2]), "=r"(r[3]) : "r"(addr));
}

__device__ __forceinline__ void ldm4t(uint32_t* r, uint32_t addr) {
    asm volatile("ldmatrix.sync.aligned.m8n8.x4.trans.shared.b16 {%0,%1,%2,%3}, [%4];"
                 : "=r"(r[0]), "=r"(r[1]), "=r"(r[2]), "=r"(r[3]) : "r"(addr));
}

__device__ __forceinline__ void mma_bf16(float* c, const uint32_t* a,
                                         uint32_t b0, uint32_t b1) {
    asm volatile(
        "mma.sync.aligned.m16n8k16.row.col.f32.bf16.bf16.f32 "
        "{%0,%1,%2,%3}, {%4,%5,%6,%7}, {%8,%9}, {%0,%1,%2,%3};"
        : "+f"(c[0]), "+f"(c[1]), "+f"(c[2]), "+f"(c[3])
        : "r"(a[0]), "r"(a[1]), "r"(a[2]), "r"(a[3]), "r"(b0), "r"(b1));
}

// split fp32 pair into packed bf16 hi (truncated) + bf16 lo (rn of residual)
__device__ __forceinline__ void split2(float v0, float v1, uint32_t& h, uint32_t& l) {
    uint32_t b0 = __float_as_uint(v0), b1 = __float_as_uint(v1);
    h = __byte_perm(b0, b1, 0x7632);
    float r0 = v0 - __uint_as_float(b0 & 0xFFFF0000u);
    float r1 = v1 - __uint_as_float(b1 & 0xFFFF0000u);
    asm("cvt.rn.bf16x2.f32 %0, %1, %2;" : "=r"(l) : "f"(r1), "f"(r0));
}

// SW128 swizzle for 128B rows
#define SWZ128(o) ((o) ^ (((o) >> 3) & 0x70))

// ---------------- sm_10Xa-only helpers -------------------------------------
#if HAS_TCGEN05
__device__ __forceinline__ uint32_t elect_one() {
    uint32_t pred;
    asm volatile(
        "{\n\t.reg .pred p;\n\telect.sync _|p, 0xFFFFFFFF;\n\t"
        "selp.b32 %0, 1, 0, p;\n\t}"
        : "=r"(pred));
    return pred;
}

__device__ __forceinline__ uint64_t mkdesc(uint32_t addr) {
    const uint64_t base = (2ull << 61) | (1ull << 46) | (64ull << 32) | (1ull << 16);
    return base | (uint64_t)((addr >> 4) & 0x3FFF);
}

__device__ __forceinline__ void mma_f16_ss(uint32_t d, uint64_t ad, uint64_t bd,
                                           uint32_t idesc, uint32_t en) {
    asm volatile(
        "{\n\t.reg .pred p;\n\tsetp.ne.u32 p, %5, 0;\n\t"
        "tcgen05.mma.cta_group::1.kind::f16 [%0], %1, %2, %3, {%4, %4, %4, %4}, p;\n\t}"
        :: "r"(d), "l"(ad), "l"(bd), "r"(idesc), "r"(0u), "r"(en) : "memory");
}

#define TC_ALLOC(sa, n)   asm volatile("tcgen05.alloc.cta_group::1.sync.aligned.shared::cta.b32 [%0], %1;" :: "r"(sa), "r"((uint32_t)(n)) : "memory")
#define TC_DEALLOC(t, n)  asm volatile("tcgen05.dealloc.cta_group::1.sync.aligned.b32 %0, %1;" :: "r"(t), "r"((uint32_t)(n)))
#define TC_RELINQ()       asm volatile("tcgen05.relinquish_alloc_permit.cta_group::1.sync.aligned;")
#define TC_COMMIT(mb)     asm volatile("tcgen05.commit.cta_group::1.mbarrier::arrive::one.shared::cluster.b64 [%0];" :: "r"(mb) : "memory")
#define TC_FENCE_AFTER()  asm volatile("tcgen05.fence::after_thread_sync;" ::: "memory")
#define TC_WAIT_LD()      asm volatile("tcgen05.wait::ld.sync.aligned;" ::: "memory")
#define MBAR_INIT(mb, n)  asm volatile("mbarrier.init.shared.b64 [%0], %1;" :: "r"(mb), "r"((uint32_t)(n)) : "memory")

#define MBAR_WAIT(mb, ph) do {                                                   \
    uint32_t _m = (mb), _p = (uint32_t)(ph), _d;                                 \
    asm volatile(                                                                \
        "{\n\t.reg .pred p;\n\t"                                                 \
        "mbarrier.try_wait.parity.acquire.cta.shared::cta.b64 p, [%1], %2;\n\t"  \
        "selp.b32 %0, 1, 0, p;\n\t}"                                             \
        : "=r"(_d) : "r"(_m), "r"(_p) : "memory");                               \
    if (!_d) {                                                                   \
        asm volatile(                                                            \
            "{\n\t.reg .pred P1;\n\t"                                            \
            "WL_%=:\n\t"                                                         \
            "mbarrier.try_wait.parity.acquire.cta.shared::cta.b64 P1, [%0], %1, 0x989680;\n\t" \
            "@P1 bra.uni WD_%=;\n\t"                                             \
            "bra.uni WL_%=;\n\t"                                                 \
            "WD_%=:\n\t}"                                                        \
            :: "r"(_m), "r"(_p) : "memory");                                     \
    }                                                                            \
} while (0)

#define TC_LD_X32(r, ta)                                                         \
    asm volatile(                                                                \
        "tcgen05.ld.sync.aligned.32x32b.x32.b32 "                                \
        "{%0, %1, %2, %3, %4, %5, %6, %7, "                                      \
        " %8, %9, %10, %11, %12, %13, %14, %15, "                                \
        " %16, %17, %18, %19, %20, %21, %22, %23, "                              \
        " %24, %25, %26, %27, %28, %29, %30, %31}, [%32];"                       \
        : "=r"((r)[0]),  "=r"((r)[1]),  "=r"((r)[2]),  "=r"((r)[3]),             \
          "=r"((r)[4]),  "=r"((r)[5]),  "=r"((r)[6]),  "=r"((r)[7]),             \
          "=r"((r)[8]),  "=r"((r)[9]),  "=r"((r)[10]), "=r"((r)[11]),            \
          "=r"((r)[12]), "=r"((r)[13]), "=r"((r)[14]), "=r"((r)[15]),            \
          "=r"((r)[16]), "=r"((r)[17]), "=r"((r)[18]), "=r"((r)[19]),            \
          "=r"((r)[20]), "=r"((r)[21]), "=r"((r)[22]), "=r"((r)[23]),            \
          "=r"((r)[24]), "=r"((r)[25]), "=r"((r)[26]), "=r"((r)[27]),            \
          "=r"((r)[28]), "=r"((r)[29]), "=r"((r)[30]), "=r"((r)[31])             \
        : "r"(ta))
#endif // HAS_TCGEN05

// ---------------- fp32 -> (bf16 hi, bf16 lo) conversion --------------------
__global__ __launch_bounds__(256) void cvt_hilo(
    const float* __restrict__ in,
    __nv_bfloat16* __restrict__ hi, __nv_bfloat16* __restrict__ lo, int n4)
{
    int i = blockIdx.x * 256 + threadIdx.x;
    if (i >= n4) return;
    float4 v = ((const float4*)in)[i];
    uint32_t h0, l0, h1, l1;
    split2(v.x, v.y, h0, l0);
    split2(v.z, v.w, h1, l1);
    uint2 hh, ll;
    hh.x = h0; hh.y = h1;
    ll.x = l0; ll.y = l1;
    ((uint2*)hi)[i] = hh;
    ((uint2*)lo)[i] = ll;
}

// ---------------- bf16x3 GEMM: C[M,N]=A@W^T, tile 128x128 ------------------
// Output: fp32 (C) OR packed bf16 hi/lo (Ch/Cl), value = (acc+bias)*scale.
#define TM 128
#define TN 128

#define KB_T   64
#define NKB_T  (DMODEL / KB_T)
#define TSTG   (TM * KB_T * 2)
#define STAGE_T (4 * TSTG)
#define KB_F   32
#define NKB_F  (DMODEL / KB_F)
#define FSTG   (TM * KB_F * 2)
#define STAGE_F (4 * FSTG)

#define GEMM_DSMEM (2 * STAGE_T + 1024)
#define GEMM_IDESC ((1u << 4) | (1u << 7) | (1u << 10) | ((TN / 8) << 17) | ((TM / 16) << 24))

__device__ __forceinline__ uint32_t swz64(int row, int c16) {
    return (uint32_t)(row * 64 + ((c16 ^ ((row >> 1) & 3)) << 4));
}

#if HAS_TCGEN05
__device__ __forceinline__ void copy_tiles_t(
    const __nv_bfloat16* __restrict__ Ah, const __nv_bfloat16* __restrict__ Al,
    const __nv_bfloat16* __restrict__ Wh, const __nv_bfloat16* __restrict__ Wl,
    int m0, int n0, int kb, uint32_t base, int tid)
{
    const int koff = kb * KB_T;
#pragma unroll
    for (int i = 0; i < 4; i++) {
        int c   = tid + i * 256;
        int row = c >> 3;
        int c8  = c & 7;
        uint32_t sw = base + SWZ128(row * 128 + c8 * 16);
        cp16(sw,            Ah + (size_t)(m0 + row) * DMODEL + koff + c8 * 8);
        cp16(sw + TSTG,     Al + (size_t)(m0 + row) * DMODEL + koff + c8 * 8);
        cp16(sw + 2 * TSTG, Wh + (size_t)(n0 + row) * DMODEL + koff + c8 * 8);
        cp16(sw + 3 * TSTG, Wl + (size_t)(n0 + row) * DMODEL + koff + c8 * 8);
    }
}
#endif

__device__ __forceinline__ void copy_tiles_f(
    const __nv_bfloat16* __restrict__ Ah, const __nv_bfloat16* __restrict__ Al,
    const __nv_bfloat16* __restrict__ Wh, const __nv_bfloat16* __restrict__ Wl,
    int m0, int n0, int kb, uint32_t base, int tid)
{
    const int koff = kb * KB_F;
#pragma unroll
    for (int i = 0; i < 2; i++) {
        int c   = tid + i * 256;
        int row = c >> 2;
        int c16 = c & 3;
        uint32_t sw = base + swz64(row, c16);
        cp16(sw,            Ah + (size_t)(m0 + row) * DMODEL + koff + c16 * 8);
        cp16(sw + FSTG,     Al + (size_t)(m0 + row) * DMODEL + koff + c16 * 8);
        cp16(sw + 2 * FSTG, Wh + (size_t)(n0 + row) * DMODEL + koff + c16 * 8);
        cp16(sw + 3 * FSTG, Wl + (size_t)(n0 + row) * DMODEL + koff + c16 * 8);
    }
}

__global__ __launch_bounds__(256, 1) void gemm_tc(
    const __nv_bfloat16* __restrict__ Ah, const __nv_bfloat16* __restrict__ Al,
    const __nv_bfloat16* __restrict__ Wh, const __nv_bfloat16* __restrict__ Wl,
    const float* __restrict__ bias, float* __restrict__ C,
    __nv_bfloat16* __restrict__ Ch, __nv_bfloat16* __restrict__ Cl, float scale)
{
    extern __shared__ char dsm[];
    const int tid = threadIdx.x;
    const int wid = tid >> 5;
    const int lid = tid & 31;
    const int m0  = blockIdx.x * TM;
    const int n0  = blockIdx.y * TN;

    uint32_t draw  = smem_u32(dsm);
    uint32_t abase = (draw + 1023) & ~1023u;

#if HAS_TCGEN05
    __shared__ uint32_t s_tmem;
    __shared__ long long s_mbar[2];
    uint32_t mbar0 = smem_u32(&s_mbar[0]);
    uint32_t mbar1 = smem_u32(&s_mbar[1]);

    if (tid == 0) { MBAR_INIT(mbar0, 1); MBAR_INIT(mbar1, 1); }
    if (wid == 0) {
        TC_ALLOC(smem_u32(&s_tmem), TN);
        TC_RELINQ();
    }
    __syncthreads();
    const uint32_t tmem = s_tmem;

    int ph0 = 0, ph1 = 0;

    copy_tiles_t(Ah, Al, Wh, Wl, m0, n0, 0, abase, tid);
    CP_COMMIT();

    for (int kb = 0; kb < NKB_T; kb++) {
        const int s = kb & 1;
        if (kb + 1 < NKB_T) {
            if (kb >= 1) {
                if ((s ^ 1) == 0) { MBAR_WAIT(mbar0, ph0); ph0 ^= 1; }
                else              { MBAR_WAIT(mbar1, ph1); ph1 ^= 1; }
            }
            copy_tiles_t(Ah, Al, Wh, Wl, m0, n0, kb + 1,
                         abase + (uint32_t)(s ^ 1) * STAGE_T, tid);
            CP_COMMIT();
            CP_WAIT(1);
        } else {
            CP_WAIT(0);
        }
        asm volatile("fence.proxy.async.shared::cta;\n" ::: "memory");
        __syncthreads();

        if (wid == 0) {
            uint32_t soff = abase + (uint32_t)s * STAGE_T;
            uint64_t dah = mkdesc(soff);
            uint64_t dal = mkdesc(soff + TSTG);
            uint64_t dbh = mkdesc(soff + 2 * TSTG);
            uint64_t dbl = mkdesc(soff + 3 * TSTG);
            if (elect_one()) {
#pragma unroll
                for (int ks = 0; ks < 4; ks++) {
                    uint32_t en0 = (kb == 0 && ks == 0) ? 0u : 1u;
                    mma_f16_ss(tmem, dah + ks * 2, dbh + ks * 2, GEMM_IDESC, en0);
                    mma_f16_ss(tmem, dah + ks * 2, dbl + ks * 2, GEMM_IDESC, 1u);
                    mma_f16_ss(tmem, dal + ks * 2, dbh + ks * 2, GEMM_IDESC, 1u);
                }
                TC_COMMIT(s == 0 ? mbar0 : mbar1);
            }
        }
    }

    MBAR_WAIT(mbar0, ph0);
    MBAR_WAIT(mbar1, ph1);
    TC_FENCE_AFTER();

    if (wid < 4) {
        const int row = m0 + wid * 32 + lid;
#pragma unroll 1
        for (int nb = 0; nb < TN / 32; nb++) {
            uint32_t r[32];
            TC_LD_X32(r, tmem + nb * 32);
            TC_WAIT_LD();
#pragma unroll
            for (int c = 0; c < 32; c += 4) {
                int col = n0 + nb * 32 + c;
                float v0 = (__uint_as_float(r[c + 0]) + bias[col + 0]) * scale;
                float v1 = (__uint_as_float(r[c + 1]) + bias[col + 1]) * scale;
                float v2 = (__uint_as_float(r[c + 2]) + bias[col + 2]) * scale;
                float v3 = (__uint_as_float(r[c + 3]) + bias[col + 3]) * scale;
                size_t idx = (size_t)row * DMODEL + col;
                if (Ch) {
                    uint32_t h0, l0, h1, l1;
                    split2(v0, v1, h0, l0);
                    split2(v2, v3, h1, l1);
                    *(uint32_t*)(Ch + idx)     = h0;
                    *(uint32_t*)(Cl + idx)     = l0;
                    *(uint32_t*)(Ch + idx + 2) = h1;
                    *(uint32_t*)(Cl + idx + 2) = l1;
                } else {
                    float4 o; o.x = v0; o.y = v1; o.z = v2; o.w = v3;
                    *(float4*)(C + idx) = o;
                }
            }
        }
    }
    __syncthreads();
    if (wid == 0) TC_DEALLOC(tmem, TN);

#else
    // ---------------- mma.sync bf16x3 fallback ----------------
    const int wm = wid >> 1;
    const int wn = wid & 1;

    float acc[2][8][4];
#pragma unroll
    for (int mt = 0; mt < 2; mt++)
#pragma unroll
        for (int nt = 0; nt < 8; nt++)
#pragma unroll
            for (int j = 0; j < 4; j++) acc[mt][nt][j] = 0.0f;

    const int lrow = (lid & 7) + ((lid >> 3) & 1) * 8;
    const int lhalf = lid >> 4;

    copy_tiles_f(Ah, Al, Wh, Wl, m0, n0, 0, abase, tid);
    CP_COMMIT();

    for (int kb = 0; kb < NKB_F; kb++) {
        const uint32_t sbase = abase + (uint32_t)(kb & 1) * STAGE_F;
        if (kb + 1 < NKB_F) {
            copy_tiles_f(Ah, Al, Wh, Wl, m0, n0, kb + 1,
                         abase + (uint32_t)((kb + 1) & 1) * STAGE_F, tid);
            CP_COMMIT();
            CP_WAIT(1);
        } else {
            CP_WAIT(0);
        }
        __syncthreads();

#pragma unroll
        for (int ks = 0; ks < 2; ks++) {
            const int chunk = ks * 2 + lhalf;
            uint32_t bh[4][4], bl[4][4];
#pragma unroll
            for (int nt = 0; nt < 4; nt++) {
                int brow = wn * 64 + nt * 16 + lrow;
                uint32_t boff = swz64(brow, chunk);
                ldm4(bh[nt], sbase + 2 * FSTG + boff);
                ldm4(bl[nt], sbase + 3 * FSTG + boff);
            }
#pragma unroll
            for (int mt = 0; mt < 2; mt++) {
                int arow = wm * 32 + mt * 16 + lrow;
                uint32_t aoff = swz64(arow, chunk);
                uint32_t ah[4], al[4];
                ldm4(ah, sbase + aoff);
                ldm4(al, sbase + FSTG + aoff);
#pragma unroll
                for (int nt = 0; nt < 4; nt++) {
                    mma_bf16(acc[mt][2 * nt + 0], ah, bh[nt][0], bh[nt][2]);
                    mma_bf16(acc[mt][2 * nt + 1], ah, bh[nt][1], bh[nt][3]);
                    mma_bf16(acc[mt][2 * nt + 0], ah, bl[nt][0], bl[nt][2]);
                    mma_bf16(acc[mt][2 * nt + 1], ah, bl[nt][1], bl[nt][3]);
                    mma_bf16(acc[mt][2 * nt + 0], al, bh[nt][0], bh[nt][2]);
                    mma_bf16(acc[mt][2 * nt + 1], al, bh[nt][1], bh[nt][3]);
                }
            }
        }
        __syncthreads();
    }

#pragma unroll
    for (int mt = 0; mt < 2; mt++) {
        int r0 = m0 + wm * 32 + mt * 16 + (lid >> 2);
#pragma unroll
        for (int nt = 0; nt < 8; nt++) {
            int c0 = n0 + wn * 64 + nt * 8 + (lid & 3) * 2;
            float b0 = bias[c0], b1 = bias[c0 + 1];
            float u0 = (acc[mt][nt][0] + b0) * scale;
            float u1 = (acc[mt][nt][1] + b1) * scale;
            float v0 = (acc[mt][nt][2] + b0) * scale;
            float v1 = (acc[mt][nt][3] + b1) * scale;
            size_t i0 = (size_t)r0 * DMODEL + c0;
            size_t i1 = (size_t)(r0 + 8) * DMODEL + c0;
            if (Ch) {
                uint32_t h0, l0, h1, l1;
                split2(u0, u1, h0, l0);
                split2(v0, v1, h1, l1);
                *(uint32_t*)(Ch + i0) = h0;
                *(uint32_t*)(Cl + i0) = l0;
                *(uint32_t*)(Ch + i1) = h1;
                *(uint32_t*)(Cl + i1) = l1;
            } else {
                float2 u; u.x = u0; u.y = u1;
                float2 v; v.x = v0; v.y = v1;
                *(float2*)(C + i0) = u;
                *(float2*)(C + i1) = v;
            }
        }
    }
#endif
}

// ---------------------------------------------------------------------------
// Tensor-core FlashAttention-2, bf16x3 for both QK^T and PV.
// CTA = 128 q-rows x one (b,h). 8 warps x 16 q-rows. Key tiles of 64.
// smem: Qh(16K) Ql(16K) + 2 stages of {Kh,Kl,Vh,Vl (8K each), mask(256B)}.
// ---------------------------------------------------------------------------
#define AT_STG   33792                       // 33 KB (1024-aligned stage stride)
#define AT_KVOFF 32768
#define AT_DSMEM (AT_KVOFF + 2 * AT_STG)     // 100352

__global__ __launch_bounds__(256, 1) void attn_tc(
    const __nv_bfloat16* __restrict__ Qh_, const __nv_bfloat16* __restrict__ Ql_,
    const __nv_bfloat16* __restrict__ Kh_, const __nv_bfloat16* __restrict__ Kl_,
    const __nv_bfloat16* __restrict__ Vh_, const __nv_bfloat16* __restrict__ Vl_,
    const int* __restrict__ mask,
    __nv_bfloat16* __restrict__ Oh_, __nv_bfloat16* __restrict__ Ol_)
{
    extern __shared__ char sm[];
    const uint32_t sb = smem_u32(sm);

    const int tid = threadIdx.x;
    const int w   = tid >> 5;
    const int l   = tid & 31;
    const int bh  = blockIdx.y;
    const int b   = bh >> 4;
    const int h   = bh & 15;
    const int q0  = blockIdx.x * 128;

    const size_t rowQ  = ((size_t)(b * SEQ + q0)) * DMODEL + h * DKH;
    const size_t rowK0 = ((size_t)(b * SEQ)) * DMODEL + h * DKH;
    const int*   mg    = mask + b * SEQ;

    // --- Q tiles (hi/lo) -> smem, group 0 ---
#pragma unroll
    for (int i = 0; i < 4; i++) {
        int c   = tid + i * 256;
        int row = c >> 3;
        int c8  = c & 7;
        uint32_t sw = SWZ128(row * 128 + c8 * 16);
        cp16(sb + sw,         Qh_ + rowQ + (size_t)row * DMODEL + c8 * 8);
        cp16(sb + 16384 + sw, Ql_ + rowQ + (size_t)row * DMODEL + c8 * 8);
    }
    CP_COMMIT();

    // --- K/V stage copy helper (inline twice) ---
#define AT_COPY_KV(kb_, s_) do {                                                 \
    uint32_t kvb_ = sb + AT_KVOFF + (uint32_t)(s_) * AT_STG;                     \
    _Pragma("unroll")                                                            \
    for (int i_ = 0; i_ < 1; i_++) {                                             \
        int c_   = tid + i_ * 256;                                               \
        int row_ = c_ >> 3;                                                      \
        int c8_  = c_ & 7;                                                       \
        uint32_t sw_ = SWZ128(row_ * 128 + c8_ * 16);                            \
        size_t g_ = rowK0 + (size_t)((kb_) * 64 + row_) * DMODEL + c8_ * 8;      \
        cp16(kvb_ + sw_,         Kh_ + g_);                                      \
        cp16(kvb_ + 8192 + sw_,  Kl_ + g_);                                      \
        cp16(kvb_ + 16384 + sw_, Vh_ + g_);                                      \
        cp16(kvb_ + 24576 + sw_, Vl_ + g_);                                      \
    }                                                                            \
    {                                                                            \
        int c_   = tid + 256;                                                    \
        int row_ = c_ >> 3;                                                      \
        int c8_  = c_ & 7;                                                       \
        uint32_t sw_ = SWZ128(row_ * 128 + c8_ * 16);                            \
        size_t g_ = rowK0 + (size_t)((kb_) * 64 + row_) * DMODEL + c8_ * 8;      \
        cp16(kvb_ + sw_,         Kh_ + g_);                                      \
        cp16(kvb_ + 8192 + sw_,  Kl_ + g_);                                      \
        cp16(kvb_ + 16384 + sw_, Vh_ + g_);                                      \
        cp16(kvb_ + 24576 + sw_, Vl_ + g_);                                      \
    }                                                                            \
    if (tid < 16) cp16(kvb_ + 32768 + tid * 16, mg + (kb_) * 64 + tid * 4);      \
} while (0)

    AT_COPY_KV(0, 0);
    CP_COMMIT();

    CP_WAIT(1);
    __syncthreads();

    // --- preload Q fragments (held across the whole loop) ---
    const int lrow = (l & 7) + ((l >> 3) & 1) * 8;
    const int lkb  = (l >> 4) * 16;           // 16-byte k-half select
    uint32_t qh[4][4], ql[4][4];
#pragma unroll
    for (int kt = 0; kt < 4; kt++) {
        uint32_t qa = sb + SWZ128((w * 16 + lrow) * 128 + kt * 32 + lkb);
        ldm4(qh[kt], qa);
        ldm4(ql[kt], qa + 16384);
    }

    float O[8][4];
    float S[8][4];
    float m0r = -INFINITY, m1r = -INFINITY, l0r = 0.0f, l1r = 0.0f;
#pragma unroll
    for (int nt = 0; nt < 8; nt++)
#pragma unroll
        for (int j = 0; j < 4; j++) O[nt][j] = 0.0f;

    for (int kb = 0; kb < SEQ / 64; kb++) {
        const int s = kb & 1;
        if (kb + 1 < SEQ / 64) {
            AT_COPY_KV(kb + 1, s ^ 1);
            CP_COMMIT();
            CP_WAIT(1);
        } else {
            CP_WAIT(0);
        }
        __syncthreads();

        const uint32_t kvb = sb + AT_KVOFF + (uint32_t)s * AT_STG;
        const char* kvc = sm + AT_KVOFF + (size_t)s * AT_STG;

        // ---- S = Q @ K^T (bf16x3) ----
#pragma unroll
        for (int nt = 0; nt < 8; nt++)
#pragma unroll
            for (int j = 0; j < 4; j++) S[nt][j] = 0.0f;

#pragma unroll
        for (int kt = 0; kt < 4; kt++) {
#pragma unroll
            for (int np = 0; np < 4; np++) {
                uint32_t ka = kvb + SWZ128((np * 16 + lrow) * 128 + kt * 32 + lkb);
                uint32_t kh[4], kl[4];
                ldm4(kh, ka);
                ldm4(kl, ka + 8192);
                mma_bf16(S[2 * np + 0], qh[kt], kh[0], kh[2]);
                mma_bf16(S[2 * np + 0], qh[kt], kl[0], kl[2]);
                mma_bf16(S[2 * np + 0], ql[kt], kh[0], kh[2]);
                mma_bf16(S[2 * np + 1], qh[kt], kh[1], kh[3]);
                mma_bf16(S[2 * np + 1], qh[kt], kl[1], kl[3]);
                mma_bf16(S[2 * np + 1], ql[kt], kh[1], kh[3]);
            }
        }

        // ---- mask + online softmax ----
        const int* smask = (const int*)(kvc + 32768);
        float mx0 = -INFINITY, mx1 = -INFINITY;
#pragma unroll
        for (int nt = 0; nt < 8; nt++) {
            int2 mk = *(const int2*)(smask + nt * 8 + (l & 3) * 2);
            if (mk.x == 0) { S[nt][0] = -1e9f; S[nt][2] = -1e9f; }
            if (mk.y == 0) { S[nt][1] = -1e9f; S[nt][3] = -1e9f; }
            mx0 = fmaxf(mx0, fmaxf(S[nt][0], S[nt][1]));
            mx1 = fmaxf(mx1, fmaxf(S[nt][2], S[nt][3]));
        }
        mx0 = fmaxf(mx0, __shfl_xor_sync(0xffffffffu, mx0, 1));
        mx0 = fmaxf(mx0, __shfl_xor_sync(0xffffffffu, mx0, 2));
        mx1 = fmaxf(mx1, __shfl_xor_sync(0xffffffffu, mx1, 1));
        mx1 = fmaxf(mx1, __shfl_xor_sync(0xffffffffu, mx1, 2));

        float mn0 = fmaxf(m0r, mx0);
        float mn1 = fmaxf(m1r, mx1);
        float a0 = __expf(m0r - mn0);
        float a1 = __expf(m1r - mn1);
        m0r = mn0; m1r = mn1;

        float sum0 = 0.0f, sum1 = 0.0f;
#pragma unroll
        for (int nt = 0; nt < 8; nt++) {
            S[nt][0] = __expf(S[nt][0] - mn0);
            S[nt][1] = __expf(S[nt][1] - mn0);
            S[nt][2] = __expf(S[nt][2] - mn1);
            S[nt][3] = __expf(S[nt][3] - mn1);
            sum0 += S[nt][0] + S[nt][1];
            sum1 += S[nt][2] + S[nt][3];
        }
        sum0 += __shfl_xor_sync(0xffffffffu, sum0, 1);
        sum0 += __shfl_xor_sync(0xffffffffu, sum0, 2);
        sum1 += __shfl_xor_sync(0xffffffffu, sum1, 1);
        sum1 += __shfl_xor_sync(0xffffffffu, sum1, 2);
        l0r = l0r * a0 + sum0;
        l1r = l1r * a1 + sum1;

#pragma unroll
        for (int nt = 0; nt < 8; nt++) {
            O[nt][0] *= a0; O[nt][1] *= a0;
            O[nt][2] *= a1; O[nt][3] *= a1;
        }

        // ---- O += P @ V (bf16x3) ----
#pragma unroll
        for (int kt = 0; kt < 4; kt++) {
            uint32_t ph[4], pl[4];
            split2(S[2 * kt + 0][0], S[2 * kt + 0][1], ph[0], pl[0]);
            split2(S[2 * kt + 0][2], S[2 * kt + 0][3], ph[1], pl[1]);
            split2(S[2 * kt + 1][0], S[2 * kt + 1][1], ph[2], pl[2]);
            split2(S[2 * kt + 1][2], S[2 * kt + 1][3], ph[3], pl[3]);
#pragma unroll
            for (int dp = 0; dp < 4; dp++) {
                uint32_t va = kvb + 16384 + SWZ128((kt * 16 + lrow) * 128 + dp * 32 + lkb);
                uint32_t vh[4], vl[4];
                ldm4t(vh, va);
                ldm4t(vl, va + 8192);
                mma_bf16(O[2 * dp + 0], ph, vh[0], vh[1]);
                mma_bf16(O[2 * dp + 0], ph, vl[0], vl[1]);
                mma_bf16(O[2 * dp + 0], pl, vh[0], vh[1]);
                mma_bf16(O[2 * dp + 1], ph, vh[2], vh[3]);
                mma_bf16(O[2 * dp + 1], ph, vl[2], vl[3]);
                mma_bf16(O[2 * dp + 1], pl, vh[2], vh[3]);
            }
        }
        __syncthreads();   // stage s free for the copy issued in iter kb+1
    }

    // ---- epilogue: normalize, split hi/lo, store ----
    float inv0 = 1.0f / l0r;
    float inv1 = 1.0f / l1r;
    const int r0 = b * SEQ + q0 + w * 16 + (l >> 2);
#pragma unroll
    for (int nt = 0; nt < 8; nt++) {
        size_t idx = (size_t)r0 * DMODEL + h * DKH + nt * 8 + (l & 3) * 2;
        uint32_t hA, lA, hB, lB;
        split2(O[nt][0] * inv0, O[nt][1] * inv0, hA, lA);
        split2(O[nt][2] * inv1, O[nt][3] * inv1, hB, lB);
        *(uint32_t*)(Oh_ + idx)              = hA;
        *(uint32_t*)(Ol_ + idx)              = lA;
        *(uint32_t*)(Oh_ + idx + 8 * DMODEL) = hB;
        *(uint32_t*)(Ol_ + idx + 8 * DMODEL) = lB;
    }
#undef AT_COPY_KV
}

// ---------------------------------------------------------------------------
extern "C" void kernel_launch(void* const* d_in, const int* in_sizes, int n_in,
                              void* d_out, int out_size)
{
    const float* x    = (const float*)d_in[0];
    const int*   mask = (const int*)  d_in[1];
    const float* Wq   = (const float*)d_in[2];
    const float* bq   = (const float*)d_in[3];
    const float* Wk   = (const float*)d_in[4];
    const float* bk   = (const float*)d_in[5];
    const float* Wv   = (const float*)d_in[6];
    const float* bv   = (const float*)d_in[7];
    const float* Wo   = (const float*)d_in[8];
    const float* bo   = (const float*)d_in[9];
    float* out = (float*)d_out;

    __nv_bfloat16 *xh, *xl, *wh, *wl, *qh, *ql, *kh, *kl, *vh, *vl, *ah, *al;
    cudaGetSymbolAddress((void**)&xh, g_xh);
    cudaGetSymbolAddress((void**)&xl, g_xl);
    cudaGetSymbolAddress((void**)&wh, g_wh);
    cudaGetSymbolAddress((void**)&wl, g_wl);
    cudaGetSymbolAddress((void**)&qh, g_qh);
    cudaGetSymbolAddress((void**)&ql, g_ql);
    cudaGetSymbolAddress((void**)&kh, g_kh);
    cudaGetSymbolAddress((void**)&kl, g_kl);
    cudaGetSymbolAddress((void**)&vh, g_vh);
    cudaGetSymbolAddress((void**)&vl, g_vl);
    cudaGetSymbolAddress((void**)&ah, g_ah);
    cudaGetSymbolAddress((void**)&al, g_al);

    cudaFuncSetAttribute(gemm_tc,
                         cudaFuncAttributeMaxDynamicSharedMemorySize, GEMM_DSMEM);
    cudaFuncSetAttribute(attn_tc,
                         cudaFuncAttributeMaxDynamicSharedMemorySize, AT_DSMEM);

    const int n4x = MR * DMODEL / 4;
    const int n4w = DD / 4;

    cvt_hilo<<<n4x / 256, 256>>>(x, xh, xl, n4x);
    cvt_hilo<<<n4w / 256, 256>>>(Wq, wh + 0 * (size_t)DD, wl + 0 * (size_t)DD, n4w);
    cvt_hilo<<<n4w / 256, 256>>>(Wk, wh + 1 * (size_t)DD, wl + 1 * (size_t)DD, n4w);
    cvt_hilo<<<n4w / 256, 256>>>(Wv, wh + 2 * (size_t)DD, wl + 2 * (size_t)DD, n4w);
    cvt_hilo<<<n4w / 256, 256>>>(Wo, wh + 3 * (size_t)DD, wl + 3 * (size_t)DD, n4w);

    dim3 gg(MR / TM, DMODEL / TN);   // 64 x 8
    // Q projection: fold 1/sqrt(d_k) = 0.125 into the stored Q
    gemm_tc<<<gg, 256, GEMM_DSMEM>>>(xh, xl, wh + 0 * (size_t)DD, wl + 0 * (size_t)DD,
                                     bq, nullptr, qh, ql, 0.125f);
    gemm_tc<<<gg, 256, GEMM_DSMEM>>>(xh, xl, wh + 1 * (size_t)DD, wl + 1 * (size_t)DD,
                                     bk, nullptr, kh, kl, 1.0f);
    gemm_tc<<<gg, 256, GEMM_DSMEM>>>(xh, xl, wh + 2 * (size_t)DD, wl + 2 * (size_t)DD,
                                     bv, nullptr, vh, vl, 1.0f);

    dim3 ga(SEQ / 128, BATCH * NHEADS);   // 16 x 64
    attn_tc<<<ga, 256, AT_DSMEM>>>(qh, ql, kh, kl, vh, vl, mask, ah, al);

    gemm_tc<<<gg, 256, GEMM_DSMEM>>>(ah, al, wh + 3 * (size_t)DD, wl + 3 * (size_t)DD,
                                     bo, out, nullptr, nullptr, 1.0f);
}